// round 1
// baseline (speedup 1.0000x reference)
#include <cuda_runtime.h>
#include <cuda_bf16.h>
#include <math.h>

// Problem constants
#define BB 4
#define NN 4096
#define KK 32
#define CC 3
#define DD 64
#define DP 128
#define DC 69           // C + D + 2
#define NPTS (BB*NN)    // 16384
#define ALPHA 0.2f

// Scratch for pooled [NPTS, DP] (no cudaMalloc allowed)
__device__ float g_pooled[NPTS * DP];

// ---------- packed f32x2 helpers (FFMA2 path, PTX-only per sm_103a) ----------
__device__ __forceinline__ void ffma2(unsigned long long& acc,
                                      unsigned long long a,
                                      unsigned long long b) {
    asm("fma.rn.f32x2 %0, %1, %2, %0;" : "+l"(acc) : "l"(a), "l"(b));
}
__device__ __forceinline__ unsigned long long pk(float x, float y) {
    unsigned long long r;
    asm("mov.b64 %0, {%1, %2};" : "=l"(r) : "f"(x), "f"(y));
    return r;
}
__device__ __forceinline__ float2 upk(unsigned long long v) {
    float2 r;
    asm("mov.b64 {%0, %1}, %2;" : "=f"(r.x), "=f"(r.y) : "l"(v));
    return r;
}

// ============================================================================
// Kernel 1: e = leaky_relu(nfn @ a); att = softmax_k(e); pooled = sum_k att*nfn
// Block = 128 threads (1 per output channel d). a cached in SMEM packed in
// j-pairs so the inner loop is pure LDS.64/LDS.128 + FFMA2.
// ============================================================================
__global__ void attn_kernel(const float* __restrict__ nfn,
                            const float* __restrict__ a) {
    extern __shared__ char sm[];
    unsigned long long* a_s = (unsigned long long*)sm;        // [64][128] = 64 KB
    float* nfn_s = (float*)(sm + 64 * 128 * 8);               // [32][128] = 16 KB
    const int tid = threadIdx.x;

    // Pack a: a_s[jj*128+d] = {a[2jj][d], a[2jj+1][d]}
    for (int i = tid; i < 64 * 128; i += 128) {
        int jj = i >> 7, d = i & 127;
        a_s[i] = pk(a[(2 * jj) * 128 + d], a[(2 * jj + 1) * 128 + d]);
    }
    __syncthreads();

    const int d = tid;
    for (int pt = blockIdx.x; pt < NPTS; pt += gridDim.x) {
        // cooperative load of nfn tile [32][128], coalesced float4
        const float4* src = (const float4*)(nfn + (size_t)pt * 4096);
        float4* dst = (float4*)nfn_s;
#pragma unroll
        for (int i = 0; i < 8; i++) dst[tid + 128 * i] = src[tid + 128 * i];
        __syncthreads();

        unsigned long long acc[32];
#pragma unroll
        for (int k = 0; k < 32; k++) acc[k] = 0ull;

        const ulonglong2* nv = (const ulonglong2*)nfn_s;  // row k = 32 ull2
#pragma unroll 2
        for (int jj = 0; jj < 64; jj += 2) {
            unsigned long long a0 = a_s[jj * 128 + d];
            unsigned long long a1 = a_s[jj * 128 + 128 + d];
#pragma unroll
            for (int k = 0; k < 32; k++) {
                ulonglong2 v = nv[k * 32 + (jj >> 1)];
                ffma2(acc[k], v.x, a0);
                ffma2(acc[k], v.y, a1);
            }
        }

        // leaky_relu + softmax over k, all in registers
        float e[32];
        float m = -1e30f;
#pragma unroll
        for (int k = 0; k < 32; k++) {
            float2 t = upk(acc[k]);
            float s = t.x + t.y;
            s = (s > 0.f) ? s : ALPHA * s;
            e[k] = s;
            m = fmaxf(m, s);
        }
        float sum = 0.f;
#pragma unroll
        for (int k = 0; k < 32; k++) {
            float x = __expf(e[k] - m);
            e[k] = x;
            sum += x;
        }
        float p = 0.f;
#pragma unroll
        for (int k = 0; k < 32; k++) p += e[k] * nfn_s[k * 128 + d];
        g_pooled[(size_t)pt * 128 + d] = p / sum;
        __syncthreads();
    }
}

// ============================================================================
// Kernel 2: dgf = [g-gn | f-fn | ||g-2gn|| | ||f-2fn||]; disf = dgf@w2 + b2
// ============================================================================
#define DGF_LD 72  // padded row (multiple of 4, idx 69..71 zero)

__global__ void disf_kernel(const float* __restrict__ g,
                            const float* __restrict__ f,
                            const float* __restrict__ gn,
                            const float* __restrict__ fn,
                            const float* __restrict__ w2,
                            const float* __restrict__ b2,
                            float* __restrict__ disf) {
    extern __shared__ char sm[];
    unsigned long long* w2_s = (unsigned long long*)sm;       // [35][128] = 35840 B
    float* dgf_s = (float*)(sm + 35 * 128 * 8);               // [32][72] = 9216 B
    float* fn_s = dgf_s + 32 * DGF_LD;                        // [32][64] = 8192 B
    float* gn_s = fn_s + 32 * 64;                             // [32][3]  = 384 B
    float* gf_s = gn_s + 96;                                  // g(3) + f(64)
    const int tid = threadIdx.x;

    // Pack w2 (69 rows -> 35 pairs, last hi = 0)
    for (int i = tid; i < 35 * 128; i += 128) {
        int jj = i >> 7, d = i & 127;
        float lo = w2[(2 * jj) * 128 + d];
        float hi = (2 * jj + 1 < DC) ? w2[(2 * jj + 1) * 128 + d] : 0.f;
        w2_s[i] = pk(lo, hi);
    }
    const float bias = b2[tid];
    __syncthreads();

    const int d = tid;
    const int k = tid >> 2, q = tid & 3;
    for (int pt = blockIdx.x; pt < NPTS; pt += gridDim.x) {
        // cooperative loads
        const float4* fsrc = (const float4*)(fn + (size_t)pt * 2048);
#pragma unroll
        for (int i = 0; i < 4; i++)
            ((float4*)fn_s)[tid + 128 * i] = fsrc[tid + 128 * i];
        if (tid < 96) gn_s[tid] = gn[(size_t)pt * 96 + tid];
        if (tid < 64) gf_s[3 + tid] = f[(size_t)pt * 64 + tid];
        if (tid < 3) gf_s[tid] = g[(size_t)pt * 3 + tid];
        __syncthreads();

        // build dgf: 4 threads per neighbor k
        float df2 = 0.f;
#pragma unroll
        for (int i = 0; i < 16; i++) {
            int c = q * 16 + i;
            float fv = gf_s[3 + c], fnv = fn_s[k * 64 + c];
            dgf_s[k * DGF_LD + 3 + c] = fv - fnv;
            float t = fv - 2.f * fnv;
            df2 += t * t;
        }
        df2 += __shfl_xor_sync(0xffffffffu, df2, 1);
        df2 += __shfl_xor_sync(0xffffffffu, df2, 2);
        if (q == 0) {
            float dg2 = 0.f;
#pragma unroll
            for (int c = 0; c < 3; c++) {
                float gv = gf_s[c], gnv = gn_s[k * 3 + c];
                dgf_s[k * DGF_LD + c] = gv - gnv;
                float t = gv - 2.f * gnv;
                dg2 += t * t;
            }
            dgf_s[k * DGF_LD + 67] = sqrtf(dg2);
            dgf_s[k * DGF_LD + 68] = sqrtf(df2);
        } else if (q == 1) {
            dgf_s[k * DGF_LD + 69] = 0.f;
            dgf_s[k * DGF_LD + 70] = 0.f;
            dgf_s[k * DGF_LD + 71] = 0.f;
        }
        __syncthreads();

        // GEMM [32 x 69] @ [69 x 128]
        unsigned long long acc[32];
#pragma unroll
        for (int kk = 0; kk < 32; kk++) acc[kk] = 0ull;
#pragma unroll 1
        for (int jjp = 0; jjp < 17; jjp++) {
            unsigned long long a0 = w2_s[(2 * jjp) * 128 + d];
            unsigned long long a1 = w2_s[(2 * jjp) * 128 + 128 + d];
#pragma unroll
            for (int kk = 0; kk < 32; kk++) {
                ulonglong2 v =
                    *(const ulonglong2*)(dgf_s + kk * DGF_LD + jjp * 4);
                ffma2(acc[kk], v.x, a0);
                ffma2(acc[kk], v.y, a1);
            }
        }
        {  // tail: channels 68 (df) and 69 (zero pad)
            unsigned long long a0 = w2_s[34 * 128 + d];
#pragma unroll
            for (int kk = 0; kk < 32; kk++) {
                unsigned long long v =
                    *(const unsigned long long*)(dgf_s + kk * DGF_LD + 68);
                ffma2(acc[kk], v, a0);
            }
        }

        float* outp = disf + (size_t)pt * (KK * DP) + d;
#pragma unroll
        for (int kk = 0; kk < 32; kk++) {
            float2 t = upk(acc[kk]);
            outp[kk * 128] = t.x + t.y + bias;
        }
        __syncthreads();
    }
}

// ============================================================================
// Kernel 3: out = pooled @ w1 + b1   (tiny; 4 points per iteration)
// ============================================================================
__global__ void out_kernel(const float* __restrict__ w1,
                           const float* __restrict__ b1,
                           float* __restrict__ out) {
    extern __shared__ char sm[];
    unsigned long long* w1_s = (unsigned long long*)sm;  // [64][128] = 64 KB
    float* pr = (float*)(sm + 64 * 128 * 8);             // [4][128]
    const int tid = threadIdx.x;

    for (int i = tid; i < 64 * 128; i += 128) {
        int dd = i >> 7, c = i & 127;
        w1_s[i] = pk(w1[(2 * dd) * 128 + c], w1[(2 * dd + 1) * 128 + c]);
    }
    const float bias = b1[tid];
    __syncthreads();

    const int c = tid;
    for (int grp = blockIdx.x; grp < NPTS / 4; grp += gridDim.x) {
#pragma unroll
        for (int i = 0; i < 4; i++)
            pr[tid + 128 * i] = g_pooled[(size_t)grp * 512 + tid + 128 * i];
        __syncthreads();

        unsigned long long acc0 = 0, acc1 = 0, acc2 = 0, acc3 = 0;
        const ulonglong2* pv = (const ulonglong2*)pr;
#pragma unroll 2
        for (int dd = 0; dd < 64; dd += 2) {
            unsigned long long a0 = w1_s[dd * 128 + c];
            unsigned long long a1 = w1_s[dd * 128 + 128 + c];
            ulonglong2 v0 = pv[0 * 32 + (dd >> 1)];
            ulonglong2 v1 = pv[1 * 32 + (dd >> 1)];
            ulonglong2 v2 = pv[2 * 32 + (dd >> 1)];
            ulonglong2 v3 = pv[3 * 32 + (dd >> 1)];
            ffma2(acc0, v0.x, a0); ffma2(acc0, v0.y, a1);
            ffma2(acc1, v1.x, a0); ffma2(acc1, v1.y, a1);
            ffma2(acc2, v2.x, a0); ffma2(acc2, v2.y, a1);
            ffma2(acc3, v3.x, a0); ffma2(acc3, v3.y, a1);
        }
        float2 t0 = upk(acc0), t1 = upk(acc1), t2 = upk(acc2), t3 = upk(acc3);
        float* o = out + (size_t)grp * 512 + c;
        o[0] = t0.x + t0.y + bias;
        o[128] = t1.x + t1.y + bias;
        o[256] = t2.x + t2.y + bias;
        o[384] = t3.x + t3.y + bias;
        __syncthreads();
    }
}

// ============================================================================
// launch
// ============================================================================
extern "C" void kernel_launch(void* const* d_in, const int* in_sizes, int n_in,
                              void* d_out, int out_size) {
    const float* g = (const float*)d_in[0];
    const float* f = (const float*)d_in[1];
    const float* gn = (const float*)d_in[2];
    const float* fn = (const float*)d_in[3];
    const float* nfn = (const float*)d_in[4];
    const float* a = (const float*)d_in[5];
    const float* w2 = (const float*)d_in[6];
    const float* b2 = (const float*)d_in[7];
    const float* w1 = (const float*)d_in[8];
    const float* b1 = (const float*)d_in[9];

    float* out = (float*)d_out;                      // [B,N,128]
    float* disf = out + (size_t)NPTS * DP;           // [B,N,K,128]

    const int smem_attn = 64 * 128 * 8 + 32 * 128 * 4;            // 81920
    const int smem_disf = 35 * 128 * 8 + (32 * DGF_LD + 32 * 64 + 96 + 68) * 4;
    const int smem_out = 64 * 128 * 8 + 4 * 128 * 4;              // 67584

    cudaFuncSetAttribute(attn_kernel,
                         cudaFuncAttributeMaxDynamicSharedMemorySize, smem_attn);
    cudaFuncSetAttribute(disf_kernel,
                         cudaFuncAttributeMaxDynamicSharedMemorySize, smem_disf);
    cudaFuncSetAttribute(out_kernel,
                         cudaFuncAttributeMaxDynamicSharedMemorySize, smem_out);

    attn_kernel<<<296, 128, smem_attn>>>(nfn, a);
    disf_kernel<<<592, 128, smem_disf>>>(g, f, gn, fn, w2, b2, disf);
    out_kernel<<<296, 128, smem_out>>>(w1, b1, out);
}

// round 2
// speedup vs baseline: 1.0041x; 1.0041x over previous
#include <cuda_runtime.h>
#include <cuda_bf16.h>
#include <math.h>

// Problem constants
#define BB 4
#define NN 4096
#define KK 32
#define CC 3
#define DD 64
#define DP 128
#define DC 69           // C + D + 2
#define NPTS (BB*NN)    // 16384
#define ALPHA 0.2f

// Scratch for pooled [NPTS, DP] (no cudaMalloc allowed)
__device__ float g_pooled[NPTS * DP];

// ---------- packed f32x2 helpers (FFMA2 path, PTX-only per sm_103a) ----------
__device__ __forceinline__ void ffma2(unsigned long long& acc,
                                      unsigned long long a,
                                      unsigned long long b) {
    asm("fma.rn.f32x2 %0, %1, %2, %0;" : "+l"(acc) : "l"(a), "l"(b));
}
__device__ __forceinline__ unsigned long long pk(float x, float y) {
    unsigned long long r;
    asm("mov.b64 %0, {%1, %2};" : "=l"(r) : "f"(x), "f"(y));
    return r;
}
__device__ __forceinline__ float2 upk(unsigned long long v) {
    float2 r;
    asm("mov.b64 {%0, %1}, %2;" : "=f"(r.x), "=f"(r.y) : "l"(v));
    return r;
}

// ============================================================================
// Kernel 1: e = leaky_relu(nfn @ a); att = softmax_k(e); pooled = sum_k att*nfn
// Block = 128 threads (1 per output channel d). a cached in SMEM packed in
// j-pairs so the inner loop is pure LDS.64/LDS.128 + FFMA2.
// ============================================================================
__global__ void attn_kernel(const float* __restrict__ nfn,
                            const float* __restrict__ a) {
    extern __shared__ char sm[];
    unsigned long long* a_s = (unsigned long long*)sm;        // [64][128] = 64 KB
    float* nfn_s = (float*)(sm + 64 * 128 * 8);               // [32][128] = 16 KB
    const int tid = threadIdx.x;

    // Pack a: a_s[jj*128+d] = {a[2jj][d], a[2jj+1][d]}
    for (int i = tid; i < 64 * 128; i += 128) {
        int jj = i >> 7, d = i & 127;
        a_s[i] = pk(a[(2 * jj) * 128 + d], a[(2 * jj + 1) * 128 + d]);
    }
    __syncthreads();

    const int d = tid;
    for (int pt = blockIdx.x; pt < NPTS; pt += gridDim.x) {
        // cooperative load of nfn tile [32][128], coalesced float4
        const float4* src = (const float4*)(nfn + (size_t)pt * 4096);
        float4* dst = (float4*)nfn_s;
#pragma unroll
        for (int i = 0; i < 8; i++) dst[tid + 128 * i] = src[tid + 128 * i];
        __syncthreads();

        unsigned long long acc[32];
#pragma unroll
        for (int k = 0; k < 32; k++) acc[k] = 0ull;

        const ulonglong2* nv = (const ulonglong2*)nfn_s;  // row k = 32 ull2
#pragma unroll 2
        for (int jj = 0; jj < 64; jj += 2) {
            unsigned long long a0 = a_s[jj * 128 + d];
            unsigned long long a1 = a_s[jj * 128 + 128 + d];
#pragma unroll
            for (int k = 0; k < 32; k++) {
                ulonglong2 v = nv[k * 32 + (jj >> 1)];
                ffma2(acc[k], v.x, a0);
                ffma2(acc[k], v.y, a1);
            }
        }

        // leaky_relu + softmax over k, all in registers
        float e[32];
        float m = -1e30f;
#pragma unroll
        for (int k = 0; k < 32; k++) {
            float2 t = upk(acc[k]);
            float s = t.x + t.y;
            s = (s > 0.f) ? s : ALPHA * s;
            e[k] = s;
            m = fmaxf(m, s);
        }
        float sum = 0.f;
#pragma unroll
        for (int k = 0; k < 32; k++) {
            float x = __expf(e[k] - m);
            e[k] = x;
            sum += x;
        }
        float p = 0.f;
#pragma unroll
        for (int k = 0; k < 32; k++) p += e[k] * nfn_s[k * 128 + d];
        g_pooled[(size_t)pt * 128 + d] = p / sum;
        __syncthreads();
    }
}

// ============================================================================
// Kernel 2: dgf = [g-gn | f-fn | ||g-2gn|| | ||f-2fn||]; disf = dgf@w2 + b2
// ============================================================================
#define DGF_LD 72  // padded row (multiple of 4, idx 69..71 zero)

__global__ void disf_kernel(const float* __restrict__ g,
                            const float* __restrict__ f,
                            const float* __restrict__ gn,
                            const float* __restrict__ fn,
                            const float* __restrict__ w2,
                            const float* __restrict__ b2,
                            float* __restrict__ disf) {
    extern __shared__ char sm[];
    unsigned long long* w2_s = (unsigned long long*)sm;       // [35][128] = 35840 B
    float* dgf_s = (float*)(sm + 35 * 128 * 8);               // [32][72] = 9216 B
    float* fn_s = dgf_s + 32 * DGF_LD;                        // [32][64] = 8192 B
    float* gn_s = fn_s + 32 * 64;                             // [32][3]  = 384 B
    float* gf_s = gn_s + 96;                                  // g(3) + f(64)
    const int tid = threadIdx.x;

    // Pack w2 (69 rows -> 35 pairs, last hi = 0)
    for (int i = tid; i < 35 * 128; i += 128) {
        int jj = i >> 7, d = i & 127;
        float lo = w2[(2 * jj) * 128 + d];
        float hi = (2 * jj + 1 < DC) ? w2[(2 * jj + 1) * 128 + d] : 0.f;
        w2_s[i] = pk(lo, hi);
    }
    const float bias = b2[tid];
    __syncthreads();

    const int d = tid;
    const int k = tid >> 2, q = tid & 3;
    for (int pt = blockIdx.x; pt < NPTS; pt += gridDim.x) {
        // cooperative loads
        const float4* fsrc = (const float4*)(fn + (size_t)pt * 2048);
#pragma unroll
        for (int i = 0; i < 4; i++)
            ((float4*)fn_s)[tid + 128 * i] = fsrc[tid + 128 * i];
        if (tid < 96) gn_s[tid] = gn[(size_t)pt * 96 + tid];
        if (tid < 64) gf_s[3 + tid] = f[(size_t)pt * 64 + tid];
        if (tid < 3) gf_s[tid] = g[(size_t)pt * 3 + tid];
        __syncthreads();

        // build dgf: 4 threads per neighbor k
        float df2 = 0.f;
#pragma unroll
        for (int i = 0; i < 16; i++) {
            int c = q * 16 + i;
            float fv = gf_s[3 + c], fnv = fn_s[k * 64 + c];
            dgf_s[k * DGF_LD + 3 + c] = fv - fnv;
            float t = fv - 2.f * fnv;
            df2 += t * t;
        }
        df2 += __shfl_xor_sync(0xffffffffu, df2, 1);
        df2 += __shfl_xor_sync(0xffffffffu, df2, 2);
        if (q == 0) {
            float dg2 = 0.f;
#pragma unroll
            for (int c = 0; c < 3; c++) {
                float gv = gf_s[c], gnv = gn_s[k * 3 + c];
                dgf_s[k * DGF_LD + c] = gv - gnv;
                float t = gv - 2.f * gnv;
                dg2 += t * t;
            }
            dgf_s[k * DGF_LD + 67] = sqrtf(dg2);
            dgf_s[k * DGF_LD + 68] = sqrtf(df2);
        } else if (q == 1) {
            dgf_s[k * DGF_LD + 69] = 0.f;
            dgf_s[k * DGF_LD + 70] = 0.f;
            dgf_s[k * DGF_LD + 71] = 0.f;
        }
        __syncthreads();

        // GEMM [32 x 69] @ [69 x 128]
        unsigned long long acc[32];
#pragma unroll
        for (int kk = 0; kk < 32; kk++) acc[kk] = 0ull;
#pragma unroll 1
        for (int jjp = 0; jjp < 17; jjp++) {
            unsigned long long a0 = w2_s[(2 * jjp) * 128 + d];
            unsigned long long a1 = w2_s[(2 * jjp) * 128 + 128 + d];
#pragma unroll
            for (int kk = 0; kk < 32; kk++) {
                ulonglong2 v =
                    *(const ulonglong2*)(dgf_s + kk * DGF_LD + jjp * 4);
                ffma2(acc[kk], v.x, a0);
                ffma2(acc[kk], v.y, a1);
            }
        }
        {  // tail: channels 68 (df) and 69 (zero pad)
            unsigned long long a0 = w2_s[34 * 128 + d];
#pragma unroll
            for (int kk = 0; kk < 32; kk++) {
                unsigned long long v =
                    *(const unsigned long long*)(dgf_s + kk * DGF_LD + 68);
                ffma2(acc[kk], v, a0);
            }
        }

        float* outp = disf + (size_t)pt * (KK * DP) + d;
#pragma unroll
        for (int kk = 0; kk < 32; kk++) {
            float2 t = upk(acc[kk]);
            outp[kk * 128] = t.x + t.y + bias;
        }
        __syncthreads();
    }
}

// ============================================================================
// Kernel 3: out = pooled @ w1 + b1   (tiny; 4 points per iteration)
// ============================================================================
__global__ void out_kernel(const float* __restrict__ w1,
                           const float* __restrict__ b1,
                           float* __restrict__ out) {
    extern __shared__ char sm[];
    unsigned long long* w1_s = (unsigned long long*)sm;  // [64][128] = 64 KB
    float* pr = (float*)(sm + 64 * 128 * 8);             // [4][128]
    const int tid = threadIdx.x;

    for (int i = tid; i < 64 * 128; i += 128) {
        int dd = i >> 7, c = i & 127;
        w1_s[i] = pk(w1[(2 * dd) * 128 + c], w1[(2 * dd + 1) * 128 + c]);
    }
    const float bias = b1[tid];
    __syncthreads();

    const int c = tid;
    for (int grp = blockIdx.x; grp < NPTS / 4; grp += gridDim.x) {
#pragma unroll
        for (int i = 0; i < 4; i++)
            pr[tid + 128 * i] = g_pooled[(size_t)grp * 512 + tid + 128 * i];
        __syncthreads();

        unsigned long long acc0 = 0, acc1 = 0, acc2 = 0, acc3 = 0;
        const ulonglong2* pv = (const ulonglong2*)pr;
#pragma unroll 2
        for (int dd = 0; dd < 64; dd += 2) {
            unsigned long long a0 = w1_s[dd * 128 + c];
            unsigned long long a1 = w1_s[dd * 128 + 128 + c];
            ulonglong2 v0 = pv[0 * 32 + (dd >> 1)];
            ulonglong2 v1 = pv[1 * 32 + (dd >> 1)];
            ulonglong2 v2 = pv[2 * 32 + (dd >> 1)];
            ulonglong2 v3 = pv[3 * 32 + (dd >> 1)];
            ffma2(acc0, v0.x, a0); ffma2(acc0, v0.y, a1);
            ffma2(acc1, v1.x, a0); ffma2(acc1, v1.y, a1);
            ffma2(acc2, v2.x, a0); ffma2(acc2, v2.y, a1);
            ffma2(acc3, v3.x, a0); ffma2(acc3, v3.y, a1);
        }
        float2 t0 = upk(acc0), t1 = upk(acc1), t2 = upk(acc2), t3 = upk(acc3);
        float* o = out + (size_t)grp * 512 + c;
        o[0] = t0.x + t0.y + bias;
        o[128] = t1.x + t1.y + bias;
        o[256] = t2.x + t2.y + bias;
        o[384] = t3.x + t3.y + bias;
        __syncthreads();
    }
}

// ============================================================================
// launch
// ============================================================================
extern "C" void kernel_launch(void* const* d_in, const int* in_sizes, int n_in,
                              void* d_out, int out_size) {
    const float* g = (const float*)d_in[0];
    const float* f = (const float*)d_in[1];
    const float* gn = (const float*)d_in[2];
    const float* fn = (const float*)d_in[3];
    const float* nfn = (const float*)d_in[4];
    const float* a = (const float*)d_in[5];
    const float* w2 = (const float*)d_in[6];
    const float* b2 = (const float*)d_in[7];
    const float* w1 = (const float*)d_in[8];
    const float* b1 = (const float*)d_in[9];

    float* out = (float*)d_out;                      // [B,N,128]
    float* disf = out + (size_t)NPTS * DP;           // [B,N,K,128]

    const int smem_attn = 64 * 128 * 8 + 32 * 128 * 4;            // 81920
    const int smem_disf = 35 * 128 * 8 + (32 * DGF_LD + 32 * 64 + 96 + 68) * 4;
    const int smem_out = 64 * 128 * 8 + 4 * 128 * 4;              // 67584

    cudaFuncSetAttribute(attn_kernel,
                         cudaFuncAttributeMaxDynamicSharedMemorySize, smem_attn);
    cudaFuncSetAttribute(disf_kernel,
                         cudaFuncAttributeMaxDynamicSharedMemorySize, smem_disf);
    cudaFuncSetAttribute(out_kernel,
                         cudaFuncAttributeMaxDynamicSharedMemorySize, smem_out);

    attn_kernel<<<296, 128, smem_attn>>>(nfn, a);
    disf_kernel<<<592, 128, smem_disf>>>(g, f, gn, fn, w2, b2, disf);
    out_kernel<<<296, 128, smem_out>>>(w1, b1, out);
}